// round 14
// baseline (speedup 1.0000x reference)
#include <cuda_runtime.h>
#include <cuda_bf16.h>
#include <stdint.h>
#include <math.h>
#include <float.h>

#define BATCH 2
#define PROPS 300
#define NTOT  600
#define CHAN  512
#define FH    200
#define FW    200
#define NUMC  7
#define K1CL  6
#define CANDS 1800
#define DETS  100
#define DFEAT 25088
#define HID   1024
#define NEGV  -1e30f
#define BBOX_CLIP 4.135166556742356f

// GEMM tiling: BM=128, BN=128, BK=32, 2 stages -> 92KB smem -> 2 CTAs/SM
#define BM 128
#define BN 128
#define BK 32
#define ASTR 56        // A row stride (bf16): 112B = 7x16B
#define BSTR 136       // B row stride (bf16): 272B = 17x16B
#define A_UNIT (BM * ASTR)          // 7168
#define B_UNIT (BK * BSTR)          // 4352
#define OFF_A(buf, sp) (((buf) * 2 + (sp)) * A_UNIT)
#define OFF_B(buf, sp) (4 * A_UNIT + ((buf) * 2 + (sp)) * B_UNIT)
#define SMEM_BYTES ((4 * A_UNIT + 4 * B_UNIT) * 2)   // 92160

#define N4W1 (DFEAT * HID / 4)      // 6422528
#define NB_FAT 64000                // 12800 groups of 5 (3 roi + 2 split1)

__device__ __nv_bfloat16 g_ah[NTOT * DFEAT];
__device__ __nv_bfloat16 g_al[NTOT * DFEAT];
__device__ __nv_bfloat16 g_w1h[DFEAT * HID];
__device__ __nv_bfloat16 g_w1l[DFEAT * HID];
__device__ __nv_bfloat16 g_w2h[HID * HID];
__device__ __nv_bfloat16 g_w2l[HID * HID];
__device__ __nv_bfloat16 g_h1h[NTOT * HID];
__device__ __nv_bfloat16 g_h1l[NTOT * HID];
__device__ float g_h2[NTOT * HID];
__device__ float g_part[14 * NTOT * HID];
__device__ float g_wt[35 * HID];
__device__ float g_logits[NTOT * NUMC];
__device__ float g_deltas[NTOT * NUMC * 4];
__device__ float g_cbox[BATCH * CANDS * 4];
__device__ float g_cob[BATCH * CANDS * 4];
__device__ float g_carea[BATCH * CANDS];
__device__ float g_cscore[BATCH * CANDS];
__device__ float g_csw[BATCH * CANDS];
__device__ int   g_clab[BATCH * CANDS];

__device__ __forceinline__ uint32_t smem_u32(const void* p) {
    uint32_t r;
    asm("{ .reg .u64 t; cvta.to.shared.u64 t, %1; cvt.u32.u64 %0, t; }" : "=r"(r) : "l"(p));
    return r;
}
__device__ __forceinline__ void cp16(uint32_t saddr, const void* g, int sz) {
    asm volatile("cp.async.cg.shared.global [%0], [%1], 16, %2;\n" :: "r"(saddr), "l"(g), "r"(sz));
}
__device__ __forceinline__ void ldsm_x4(uint32_t a[4], uint32_t addr) {
    asm volatile("ldmatrix.sync.aligned.m8n8.x4.shared.b16 {%0,%1,%2,%3}, [%4];"
                 : "=r"(a[0]), "=r"(a[1]), "=r"(a[2]), "=r"(a[3]) : "r"(addr));
}
__device__ __forceinline__ void ldsm_x4_t(uint32_t a[4], uint32_t addr) {
    asm volatile("ldmatrix.sync.aligned.m8n8.x4.trans.shared.b16 {%0,%1,%2,%3}, [%4];"
                 : "=r"(a[0]), "=r"(a[1]), "=r"(a[2]), "=r"(a[3]) : "r"(addr));
}
__device__ __forceinline__ void mma_bf16(float c[4], const uint32_t a[4], uint32_t b0, uint32_t b1) {
    asm volatile("mma.sync.aligned.m16n8k16.row.col.f32.bf16.bf16.f32 "
                 "{%0,%1,%2,%3},{%4,%5,%6,%7},{%8,%9},{%0,%1,%2,%3};"
                 : "+f"(c[0]), "+f"(c[1]), "+f"(c[2]), "+f"(c[3])
                 : "r"(a[0]), "r"(a[1]), "r"(a[2]), "r"(a[3]), "r"(b0), "r"(b1));
}

// ---------------- split body (device) ----------------
__device__ __forceinline__ void split_body(const float4* __restrict__ src,
                                           __nv_bfloat162* __restrict__ dh,
                                           __nv_bfloat162* __restrict__ dl,
                                           int i, int n4) {
    if (i >= n4) return;
    float4 v = src[i];
    __nv_bfloat16 h0 = __float2bfloat16(v.x), h1 = __float2bfloat16(v.y);
    __nv_bfloat16 h2 = __float2bfloat16(v.z), h3 = __float2bfloat16(v.w);
    dh[i * 2 + 0] = __nv_bfloat162{h0, h1};
    dh[i * 2 + 1] = __nv_bfloat162{h2, h3};
    dl[i * 2 + 0] = __nv_bfloat162{__float2bfloat16(v.x - __bfloat162float(h0)),
                                   __float2bfloat16(v.y - __bfloat162float(h1))};
    dl[i * 2 + 1] = __nv_bfloat162{__float2bfloat16(v.z - __bfloat162float(h2)),
                                   __float2bfloat16(v.w - __bfloat162float(h3))};
}

// ---------------- roi body (device) ----------------
__device__ void roi_body(const float* __restrict__ feat,
                         const float* __restrict__ prop, int rid) {
    const int n = rid >> 6, c0 = (rid & 63) << 3;
    const int b = n / PROPS, tid = threadIdx.x;
    const int lane = tid & 31, wid = tid >> 5;
    const float px0 = prop[n * 4 + 0] * 0.25f, py0 = prop[n * 4 + 1] * 0.25f;
    const float px1 = prop[n * 4 + 2] * 0.25f, py1 = prop[n * 4 + 3] * 0.25f;
    const float bw = fmaxf(px1 - px0, 1.0f) * (1.0f / 7.0f);
    const float bh = fmaxf(py1 - py0, 1.0f) * (1.0f / 7.0f);

    __shared__ float sm[8 * 30 * 31];
    __shared__ int sx0[14], sx1[14], sy0[14], sy1[14];
    __shared__ float slx[14], sly[14];
    __shared__ int sb[4];

    if (tid < 14) {
        float g = ((float)tid + 0.5f) * 0.5f;
        float xc = fminf(fmaxf(px0 + g * bw, 0.0f), (float)(FW - 1));
        float yc = fminf(fmaxf(py0 + g * bh, 0.0f), (float)(FH - 1));
        int x0 = (int)floorf(xc), y0 = (int)floorf(yc);
        sx0[tid] = x0; sy0[tid] = y0;
        sx1[tid] = min(x0 + 1, FW - 1);
        sy1[tid] = min(y0 + 1, FH - 1);
        slx[tid] = xc - (float)x0;
        sly[tid] = yc - (float)y0;
    }
    __syncthreads();
    if (tid == 0) {
        sb[0] = sx0[0]; sb[1] = sy0[0];
        sb[2] = min(sx1[13] - sx0[0] + 1, 30);
        sb[3] = min(sy1[13] - sy0[0] + 1, 30);
    }
    __syncthreads();
    const int ixlo = sb[0], iylo = sb[1], wreg = sb[2], hreg = sb[3];
    const int wstr = wreg | 1;
    const int spx = hreg * wstr;

    {
        const int c = wid;
        const float* gsrc = feat + (((size_t)(b * CHAN + c0 + c) * FH) + iylo) * FW + ixlo + lane;
        float* sdst = &sm[c * spx] + lane;
        if (lane < wreg) {
            for (int y = 0; y < hreg; y++) sdst[y * wstr] = gsrc[y * FW];
        }
    }
    __syncthreads();

    for (int t = tid; t < 8 * 49; t += 256) {
        int c = t / 49, bin = t - c * 49;
        int by = bin / 7, bx = bin - by * 7;
        const float* base = &sm[c * spx];
        float acc = 0.0f;
#pragma unroll
        for (int sy = 0; sy < 2; sy++) {
            int s_y = by * 2 + sy;
            int ry0 = sy0[s_y] - iylo, ry1 = sy1[s_y] - iylo;
            float ly = sly[s_y];
#pragma unroll
            for (int sx = 0; sx < 2; sx++) {
                int s_x = bx * 2 + sx;
                int rx0 = sx0[s_x] - ixlo, rx1 = sx1[s_x] - ixlo;
                float lx = slx[s_x];
                acc += (1.0f - ly) * ((1.0f - lx) * base[ry0 * wstr + rx0] + lx * base[ry0 * wstr + rx1])
                     + ly * ((1.0f - lx) * base[ry1 * wstr + rx0] + lx * base[ry1 * wstr + rx1]);
            }
        }
        float v = acc * 0.25f;
        int idx = n * DFEAT + (c0 + c) * 49 + bin;
        __nv_bfloat16 hi = __float2bfloat16(v);
        g_ah[idx] = hi;
        g_al[idx] = __float2bfloat16(v - __bfloat162float(hi));
    }
}

// ================== fat kernel: interleaved roi (3) + split_w1 (2) ==================
__global__ void fat_pre(const float* __restrict__ feat, const float* __restrict__ prop,
                        const float4* __restrict__ w1) {
    const int bid = blockIdx.x;
    const int g5 = bid / 5;
    const int r = bid - g5 * 5;
    if (r < 3) {
        roi_body(feat, prop, g5 * 3 + r);
    } else {
        int sid = g5 * 2 + (r - 3);
        if (sid < (N4W1 + 255) / 256) {
            int i = sid * 256 + threadIdx.x;
            split_body(w1, (__nv_bfloat162*)g_w1h, (__nv_bfloat162*)g_w1l, i, N4W1);
        }
    }
}

__global__ void split_kernel(const float4* __restrict__ src,
                             __nv_bfloat162* __restrict__ dh,
                             __nv_bfloat162* __restrict__ dl, int n4) {
    int i = blockIdx.x * blockDim.x + threadIdx.x;
    split_body(src, dh, dl, i, n4);
}

__global__ void wt_build(const float* __restrict__ wc, const float* __restrict__ wb) {
    int idx = blockIdx.x * blockDim.x + threadIdx.x;
    if (idx >= 35 * HID) return;
    int o = idx >> 10, k = idx & 1023;
    g_wt[idx] = (o < 7) ? wc[k * 7 + o] : wb[k * 28 + (o - 7)];
}

// ================== GEMM: BM=128 BN=128 BK=32, 2-stage, 2 CTAs/SM ==================
#define ISSUE_TILE(kt_, buf_) do {                                                        \
    int kb = kbase + (kt_) * BK;                                                          \
    _Pragma("unroll")                                                                     \
    for (int sp = 0; sp < 2; sp++) {                                                      \
        const __nv_bfloat16* Ag = sp ? Al : Ah;                                           \
        _Pragma("unroll")                                                                 \
        for (int i = 0; i < 2; i++) {                                                     \
            int row = arow0 + 64 * i;                                                     \
            int gr = m0 + row;                                                            \
            int sz = (gr < NTOT) ? 16 : 0;                                                \
            int grc = (gr < NTOT) ? gr : (NTOT - 1);                                      \
            const void* g = (const void*)(Ag + (size_t)grc * K + kb + kc * 8);            \
            cp16(sbase + (uint32_t)(OFF_A(buf_, sp) + row * ASTR + kc * 8) * 2, g, sz);   \
        }                                                                                 \
        const __nv_bfloat16* Bg = sp ? Bl : Bh;                                           \
        _Pragma("unroll")                                                                 \
        for (int i = 0; i < 2; i++) {                                                     \
            int kr = bkr0 + 16 * i;                                                       \
            const void* g = (const void*)(Bg + (size_t)(kb + kr) * HID + n0 + nc8);       \
            cp16(sbase + (uint32_t)(OFF_B(buf_, sp) + kr * BSTR + nc8) * 2, g, 16);       \
        }                                                                                 \
    }                                                                                     \
    asm volatile("cp.async.commit_group;\n" ::);                                          \
} while (0)

__global__ __launch_bounds__(256, 2)
void mma_gemm(const __nv_bfloat16* __restrict__ Ah, const __nv_bfloat16* __restrict__ Al,
              const __nv_bfloat16* __restrict__ Bh, const __nv_bfloat16* __restrict__ Bl,
              float* __restrict__ part, int K, int KPC) {
    extern __shared__ __align__(16) char smem_raw[];
    const uint32_t sbase = smem_u32(smem_raw);
    const int t = threadIdx.x, lane = t & 31, wid = t >> 5;
    const int wm = wid & 3, wn = wid >> 2;          // 4x32 M, 2x64 N
    const int m0 = blockIdx.x * BM, n0 = blockIdx.y * BN;
    const int s = blockIdx.z;
    const int kbase = s * KPC;
    const int T = KPC / BK;
    const int arow0 = t >> 2, kc = t & 3;
    const int bkr0 = t >> 4, nc8 = (t & 15) * 8;

    float acc[2][8][4];
#pragma unroll
    for (int i = 0; i < 2; i++)
#pragma unroll
        for (int j = 0; j < 8; j++)
#pragma unroll
            for (int q = 0; q < 4; q++) acc[i][j][q] = 0.0f;

    const int a_lrow = lane & 15, a_lk = (lane >> 4) * 8;
    const int b_lk = lane & 15, b_ln = (lane >> 4) * 8;

    ISSUE_TILE(0, 0);
    for (int kt = 0; kt < T; kt++) {
        int buf = kt & 1;
        if (kt + 1 < T) ISSUE_TILE(kt + 1, (kt + 1) & 1);
        else asm volatile("cp.async.commit_group;\n" ::);
        asm volatile("cp.async.wait_group 1;\n" ::);
        __syncthreads();

#pragma unroll
        for (int kk = 0; kk < 2; kk++) {
            uint32_t bhh[16], bll[16];
#pragma unroll
            for (int nfp = 0; nfp < 4; nfp++) {
                ldsm_x4_t(&bhh[nfp * 4], sbase +
                    (uint32_t)(OFF_B(buf, 0) + (kk * 16 + b_lk) * BSTR + wn * 64 + nfp * 16 + b_ln) * 2);
                ldsm_x4_t(&bll[nfp * 4], sbase +
                    (uint32_t)(OFF_B(buf, 1) + (kk * 16 + b_lk) * BSTR + wn * 64 + nfp * 16 + b_ln) * 2);
            }
#pragma unroll
            for (int mi = 0; mi < 2; mi++) {
                uint32_t ah[4], al[4];
                ldsm_x4(ah, sbase +
                    (uint32_t)(OFF_A(buf, 0) + (wm * 32 + mi * 16 + a_lrow) * ASTR + kk * 16 + a_lk) * 2);
                ldsm_x4(al, sbase +
                    (uint32_t)(OFF_A(buf, 1) + (wm * 32 + mi * 16 + a_lrow) * ASTR + kk * 16 + a_lk) * 2);
#pragma unroll
                for (int nf = 0; nf < 8; nf++) {
                    mma_bf16(acc[mi][nf], ah, bhh[2 * nf], bhh[2 * nf + 1]);
                    mma_bf16(acc[mi][nf], ah, bll[2 * nf], bll[2 * nf + 1]);
                    mma_bf16(acc[mi][nf], al, bhh[2 * nf], bhh[2 * nf + 1]);
                }
            }
        }
        __syncthreads();
    }

    const size_t pbase = (size_t)s * NTOT * HID;
#pragma unroll
    for (int mi = 0; mi < 2; mi++) {
        int r0 = m0 + wm * 32 + mi * 16 + (lane >> 2);
        int r1 = r0 + 8;
#pragma unroll
        for (int nf = 0; nf < 8; nf++) {
            int col = n0 + wn * 64 + nf * 8 + (lane & 3) * 2;
            if (r0 < NTOT) {
                float2 v = {acc[mi][nf][0], acc[mi][nf][1]};
                *(float2*)&part[pbase + (size_t)r0 * HID + col] = v;
            }
            if (r1 < NTOT) {
                float2 v = {acc[mi][nf][2], acc[mi][nf][3]};
                *(float2*)&part[pbase + (size_t)r1 * HID + col] = v;
            }
        }
    }
}

__global__ void reduce_k(const float* __restrict__ part, const float* __restrict__ bias,
                         int S, int mode,
                         __nv_bfloat16* __restrict__ oh, __nv_bfloat16* __restrict__ ol,
                         float* __restrict__ of) {
    int idx = blockIdx.x * blockDim.x + threadIdx.x;
    if (idx >= NTOT * HID) return;
    float v = 0.0f;
    for (int s = 0; s < S; s++) v += part[(size_t)s * NTOT * HID + idx];
    v = fmaxf(v + bias[idx & 1023], 0.0f);
    if (mode == 0) {
        __nv_bfloat16 hi = __float2bfloat16(v);
        oh[idx] = hi;
        ol[idx] = __float2bfloat16(v - __bfloat162float(hi));
    } else of[idx] = v;
}

__global__ void heads_kernel(const float* __restrict__ h,
                             const float* __restrict__ bc,
                             const float* __restrict__ bb) {
    const int n = blockIdx.x, tid = threadIdx.x, lane = tid & 31, wid = tid >> 5;
    __shared__ float row[HID];
    for (int t = tid; t < HID; t += 256) row[t] = h[n * HID + t];
    __syncthreads();
    for (int j = 0; j < 5; j++) {
        int o = wid + 8 * j;
        if (o >= 35) break;
        const float* w = &g_wt[o * HID];
        float v = 0.0f;
        for (int k = lane; k < HID; k += 32) v += row[k] * w[k];
#pragma unroll
        for (int off = 16; off > 0; off >>= 1) v += __shfl_down_sync(0xffffffffu, v, off);
        if (lane == 0) {
            if (o < 7) g_logits[n * 7 + o] = v + bc[o];
            else       g_deltas[n * 28 + (o - 7)] = v + bb[o - 7];
        }
    }
}

__global__ void decode_kernel(const float* __restrict__ prop) {
    int m = blockIdx.x * blockDim.x + threadIdx.x;
    if (m >= NTOT * K1CL) return;
    int n = m / K1CL, k = 1 + (m - n * K1CL);
    int b = n / PROPS, p = n - b * PROPS;
    float l[7];
#pragma unroll
    for (int i = 0; i < 7; i++) l[i] = g_logits[n * 7 + i];
    float mx = l[0];
#pragma unroll
    for (int i = 1; i < 7; i++) mx = fmaxf(mx, l[i]);
    float s = 0.0f;
#pragma unroll
    for (int i = 0; i < 7; i++) s += expf(l[i] - mx);
    float pr = expf(l[k] - mx) / s;
    float p0 = prop[n * 4 + 0], p1 = prop[n * 4 + 1];
    float p2 = prop[n * 4 + 2], p3 = prop[n * 4 + 3];
    float w = p2 - p0, h = p3 - p1;
    float cx = p0 + 0.5f * w, cy = p1 + 0.5f * h;
    const float* d = &g_deltas[n * 28 + k * 4];
    float dx = d[0] / 10.0f, dy = d[1] / 10.0f;
    float dw = fminf(d[2] / 5.0f, BBOX_CLIP), dh = fminf(d[3] / 5.0f, BBOX_CLIP);
    float pcx = dx * w + cx, pcy = dy * h + cy;
    float pw = expf(dw) * w, ph = expf(dh) * h;
    float x1 = fminf(fmaxf(pcx - 0.5f * pw, 0.0f), 800.0f);
    float y1 = fminf(fmaxf(pcy - 0.5f * ph, 0.0f), 800.0f);
    float x2 = fminf(fmaxf(pcx + 0.5f * pw, 0.0f), 800.0f);
    float y2 = fminf(fmaxf(pcy + 0.5f * ph, 0.0f), 800.0f);
    int ci = b * CANDS + p * K1CL + (k - 1);
    g_cbox[ci * 4 + 0] = x1; g_cbox[ci * 4 + 1] = y1;
    g_cbox[ci * 4 + 2] = x2; g_cbox[ci * 4 + 3] = y2;
    float off = (float)k * 802.0f;
    float ox1 = x1 + off, oy1 = y1 + off, ox2 = x2 + off, oy2 = y2 + off;
    g_cob[ci * 4 + 0] = ox1; g_cob[ci * 4 + 1] = oy1;
    g_cob[ci * 4 + 2] = ox2; g_cob[ci * 4 + 3] = oy2;
    g_carea[ci] = (ox2 - ox1) * (oy2 - oy1);
    g_cscore[ci] = pr;
    g_clab[ci] = k;
    bool valid = (pr > 0.05f) && ((x2 - x1) >= 0.01f) && ((y2 - y1) >= 0.01f);
    g_csw[ci] = valid ? pr : NEGV;
}

__global__ void nms_kernel(float* __restrict__ out) {
    const int b = blockIdx.x, tid = threadIdx.x;
    __shared__ float sob[CANDS * 4], sarea[CANDS], ssw[CANDS];
    __shared__ float rv[32];
    __shared__ int ri[32];
    __shared__ int s_j;
    __shared__ float s_s;
    __shared__ int pj[DETS];
    __shared__ float ps[DETS];
    for (int t = tid; t < CANDS; t += 1024) {
        int g = b * CANDS + t;
        sob[t * 4 + 0] = g_cob[g * 4 + 0];
        sob[t * 4 + 1] = g_cob[g * 4 + 1];
        sob[t * 4 + 2] = g_cob[g * 4 + 2];
        sob[t * 4 + 3] = g_cob[g * 4 + 3];
        sarea[t] = g_carea[g];
        ssw[t] = g_csw[g];
    }
    __syncthreads();
    const int lane = tid & 31, warp = tid >> 5;
    for (int it = 0; it < DETS; it++) {
        float bv = -FLT_MAX;
        int bi = CANDS;
        {
            float v = ssw[tid];
            if (v > bv || (v == bv && tid < bi)) { bv = v; bi = tid; }
            int i2 = tid + 1024;
            if (i2 < CANDS) {
                float v2 = ssw[i2];
                if (v2 > bv || (v2 == bv && i2 < bi)) { bv = v2; bi = i2; }
            }
        }
#pragma unroll
        for (int off = 16; off > 0; off >>= 1) {
            float ov = __shfl_down_sync(0xffffffffu, bv, off);
            int   oi = __shfl_down_sync(0xffffffffu, bi, off);
            if (ov > bv || (ov == bv && oi < bi)) { bv = ov; bi = oi; }
        }
        if (lane == 0) { rv[warp] = bv; ri[warp] = bi; }
        __syncthreads();
        if (warp == 0) {
            float v = rv[lane];
            int i = ri[lane];
#pragma unroll
            for (int off = 16; off > 0; off >>= 1) {
                float ov = __shfl_down_sync(0xffffffffu, v, off);
                int   oi = __shfl_down_sync(0xffffffffu, i, off);
                if (ov > v || (ov == v && oi < i)) { v = ov; i = oi; }
            }
            if (lane == 0) { s_j = i; s_s = v; }
        }
        __syncthreads();
        int j = s_j;
        if (tid == 0) { pj[it] = j; ps[it] = s_s; }
        float jx1 = sob[j * 4 + 0], jy1 = sob[j * 4 + 1];
        float jx2 = sob[j * 4 + 2], jy2 = sob[j * 4 + 3];
        float ja = sarea[j];
        for (int i = tid; i < CANDS; i += 1024) {
            float xx1 = fmaxf(jx1, sob[i * 4 + 0]);
            float yy1 = fmaxf(jy1, sob[i * 4 + 1]);
            float xx2 = fminf(jx2, sob[i * 4 + 2]);
            float yy2 = fminf(jy2, sob[i * 4 + 3]);
            float inter = fmaxf(xx2 - xx1, 0.0f) * fmaxf(yy2 - yy1, 0.0f);
            float iou = inter / (ja + sarea[i] - inter + 1e-9f);
            if (iou > 0.5f || i == j) ssw[i] = NEGV;
        }
        __syncthreads();
    }
    if (tid < DETS) {
        int j = pj[tid];
        bool kv = ps[tid] > -5e29f;
        float bx0 = 0, bx1 = 0, bx2 = 0, bx3 = 0, sc = 0, lb = 0;
        if (kv) {
            int g = b * CANDS + j;
            bx0 = g_cbox[g * 4 + 0]; bx1 = g_cbox[g * 4 + 1];
            bx2 = g_cbox[g * 4 + 2]; bx3 = g_cbox[g * 4 + 3];
            sc = g_cscore[g];
            lb = (float)g_clab[g];
        }
        int base = (b * DETS + tid) * 4;
        out[base + 0] = bx0; out[base + 1] = bx1;
        out[base + 2] = bx2; out[base + 3] = bx3;
        out[BATCH * DETS * 4 + b * DETS + tid] = sc;
        out[BATCH * DETS * 4 + BATCH * DETS + b * DETS + tid] = lb;
    }
}

extern "C" void kernel_launch(void* const* d_in, const int* in_sizes, int n_in,
                              void* d_out, int out_size) {
    const float* feat = (const float*)d_in[0];
    const float* prop = (const float*)d_in[1];
    const float* w1 = (const float*)d_in[2];
    const float* b1 = (const float*)d_in[3];
    const float* w2 = (const float*)d_in[4];
    const float* b2 = (const float*)d_in[5];
    const float* wc = (const float*)d_in[6];
    const float* bc = (const float*)d_in[7];
    const float* wb = (const float*)d_in[8];
    const float* bb = (const float*)d_in[9];
    float* out = (float*)d_out;

    void *p_ah, *p_al, *p_w1h, *p_w1l, *p_w2h, *p_w2l, *p_h1h, *p_h1l, *p_h2, *p_part;
    cudaGetSymbolAddress(&p_ah, g_ah);   cudaGetSymbolAddress(&p_al, g_al);
    cudaGetSymbolAddress(&p_w1h, g_w1h); cudaGetSymbolAddress(&p_w1l, g_w1l);
    cudaGetSymbolAddress(&p_w2h, g_w2h); cudaGetSymbolAddress(&p_w2l, g_w2l);
    cudaGetSymbolAddress(&p_h1h, g_h1h); cudaGetSymbolAddress(&p_h1l, g_h1l);
    cudaGetSymbolAddress(&p_h2, g_h2);   cudaGetSymbolAddress(&p_part, g_part);

    static int smem_set = 0;
    if (!smem_set) {
        cudaFuncSetAttribute(mma_gemm, cudaFuncAttributeMaxDynamicSharedMemorySize, SMEM_BYTES);
        smem_set = 1;
    }

    const int n4w2 = HID * HID / 4;

    // [0] fat: interleaved roi + split_w1 (co-resident ALU + DRAM work)
    fat_pre<<<NB_FAT, 256>>>(feat, prop, (const float4*)w1);
    // [1] split_w2, [2] wt_build (tiny)
    split_kernel<<<(n4w2 + 255) / 256, 256>>>((const float4*)w2,
        (__nv_bfloat162*)p_w2h, (__nv_bfloat162*)p_w2l, n4w2);
    wt_build<<<140, 256>>>(wc, wb);

    // [3] GEMM1 — profiled slot. grid (5,8,7) = 280 CTAs, 2/SM -> single wave.
    mma_gemm<<<dim3(5, HID / BN, 7), 256, SMEM_BYTES>>>(
        (const __nv_bfloat16*)p_ah, (const __nv_bfloat16*)p_al,
        (const __nv_bfloat16*)p_w1h, (const __nv_bfloat16*)p_w1l,
        (float*)p_part, DFEAT, 3584);
    // [4] reduce1
    reduce_k<<<(NTOT * HID + 255) / 256, 256>>>((const float*)p_part, b1, 7, 0,
        (__nv_bfloat16*)p_h1h, (__nv_bfloat16*)p_h1l, nullptr);

    // [5] GEMM2: grid (5,8,4) = 160 CTAs, KPC=256.
    mma_gemm<<<dim3(5, HID / BN, 4), 256, SMEM_BYTES>>>(
        (const __nv_bfloat16*)p_h1h, (const __nv_bfloat16*)p_h1l,
        (const __nv_bfloat16*)p_w2h, (const __nv_bfloat16*)p_w2l,
        (float*)p_part, HID, 256);
    // [6] reduce2
    reduce_k<<<(NTOT * HID + 255) / 256, 256>>>((const float*)p_part, b2, 4, 1,
        nullptr, nullptr, (float*)p_h2);

    heads_kernel<<<NTOT, 256>>>((const float*)p_h2, bc, bb);
    decode_kernel<<<(NTOT * K1CL + 255) / 256, 256>>>(prop);
    nms_kernel<<<BATCH, 1024>>>(out);
}

// round 17
// speedup vs baseline: 1.0419x; 1.0419x over previous
#include <cuda_runtime.h>
#include <cuda_bf16.h>
#include <stdint.h>
#include <math.h>
#include <float.h>

#define BATCH 2
#define PROPS 300
#define NTOT  600
#define CHAN  512
#define FH    200
#define FW    200
#define NUMC  7
#define K1CL  6
#define CANDS 1800
#define DETS  100
#define DFEAT 25088
#define HID   1024
#define NEGV  -1e30f
#define BBOX_CLIP 4.135166556742356f

#define BM 128
#define BN 256
#define BK 32
#define ASTR 56
#define BSTR 264
#define A_UNIT (BM * ASTR)
#define B_UNIT (BK * BSTR)
// 3-stage pipeline: 6 A units (3 bufs x hi/lo), 6 B units
#define OFF_A(buf, sp) (((buf) * 2 + (sp)) * A_UNIT)
#define OFF_B(buf, sp) (6 * A_UNIT + ((buf) * 2 + (sp)) * B_UNIT)
#define SMEM_BYTES ((6 * A_UNIT + 6 * B_UNIT) * 2)

__device__ __nv_bfloat16 g_ah[NTOT * DFEAT];
__device__ __nv_bfloat16 g_al[NTOT * DFEAT];
__device__ __nv_bfloat16 g_w1h[DFEAT * HID];
__device__ __nv_bfloat16 g_w1l[DFEAT * HID];
__device__ __nv_bfloat16 g_w2h[HID * HID];
__device__ __nv_bfloat16 g_w2l[HID * HID];
__device__ __nv_bfloat16 g_h1h[NTOT * HID];
__device__ __nv_bfloat16 g_h1l[NTOT * HID];
__device__ float g_h2[NTOT * HID];
__device__ float g_part[14 * NTOT * HID];
__device__ float g_wt[35 * HID];
__device__ float g_logits[NTOT * NUMC];
__device__ float g_deltas[NTOT * NUMC * 4];
__device__ float g_cbox[BATCH * CANDS * 4];
__device__ float g_cob[BATCH * CANDS * 4];
__device__ float g_carea[BATCH * CANDS];
__device__ float g_cscore[BATCH * CANDS];
__device__ float g_csw[BATCH * CANDS];
__device__ int   g_clab[BATCH * CANDS];

__device__ __forceinline__ uint32_t smem_u32(const void* p) {
    uint32_t r;
    asm("{ .reg .u64 t; cvta.to.shared.u64 t, %1; cvt.u32.u64 %0, t; }" : "=r"(r) : "l"(p));
    return r;
}
__device__ __forceinline__ void cp16(uint32_t saddr, const void* g, int sz) {
    asm volatile("cp.async.cg.shared.global [%0], [%1], 16, %2;\n" :: "r"(saddr), "l"(g), "r"(sz));
}
__device__ __forceinline__ void ldsm_x4(uint32_t a[4], uint32_t addr) {
    asm volatile("ldmatrix.sync.aligned.m8n8.x4.shared.b16 {%0,%1,%2,%3}, [%4];"
                 : "=r"(a[0]), "=r"(a[1]), "=r"(a[2]), "=r"(a[3]) : "r"(addr));
}
__device__ __forceinline__ void ldsm_x4_t(uint32_t a[4], uint32_t addr) {
    asm volatile("ldmatrix.sync.aligned.m8n8.x4.trans.shared.b16 {%0,%1,%2,%3}, [%4];"
                 : "=r"(a[0]), "=r"(a[1]), "=r"(a[2]), "=r"(a[3]) : "r"(addr));
}
__device__ __forceinline__ void mma_bf16(float c[4], const uint32_t a[4], uint32_t b0, uint32_t b1) {
    asm volatile("mma.sync.aligned.m16n8k16.row.col.f32.bf16.bf16.f32 "
                 "{%0,%1,%2,%3},{%4,%5,%6,%7},{%8,%9},{%0,%1,%2,%3};"
                 : "+f"(c[0]), "+f"(c[1]), "+f"(c[2]), "+f"(c[3])
                 : "r"(a[0]), "r"(a[1]), "r"(a[2]), "r"(a[3]), "r"(b0), "r"(b1));
}

__global__ void split_kernel(const float4* __restrict__ src,
                             __nv_bfloat162* __restrict__ dh,
                             __nv_bfloat162* __restrict__ dl, int n4) {
    int i = blockIdx.x * blockDim.x + threadIdx.x;
    if (i >= n4) return;
    float4 v = src[i];
    __nv_bfloat16 h0 = __float2bfloat16(v.x), h1 = __float2bfloat16(v.y);
    __nv_bfloat16 h2 = __float2bfloat16(v.z), h3 = __float2bfloat16(v.w);
    dh[i * 2 + 0] = __nv_bfloat162{h0, h1};
    dh[i * 2 + 1] = __nv_bfloat162{h2, h3};
    dl[i * 2 + 0] = __nv_bfloat162{__float2bfloat16(v.x - __bfloat162float(h0)),
                                   __float2bfloat16(v.y - __bfloat162float(h1))};
    dl[i * 2 + 1] = __nv_bfloat162{__float2bfloat16(v.z - __bfloat162float(h2)),
                                   __float2bfloat16(v.w - __bfloat162float(h3))};
}

__global__ void wt_build(const float* __restrict__ wc, const float* __restrict__ wb) {
    int idx = blockIdx.x * blockDim.x + threadIdx.x;
    if (idx >= 35 * HID) return;
    int o = idx >> 10, k = idx & 1023;
    g_wt[idx] = (o < 7) ? wc[k * 7 + o] : wb[k * 28 + (o - 7)];
}

// ================== RoI Align ==================
__global__ void roi_align_kernel(const float* __restrict__ feat,
                                 const float* __restrict__ prop) {
    const int n = blockIdx.x, c0 = blockIdx.y * 8, b = n / PROPS, tid = threadIdx.x;
    const int lane = tid & 31, wid = tid >> 5;
    const float px0 = prop[n * 4 + 0] * 0.25f, py0 = prop[n * 4 + 1] * 0.25f;
    const float px1 = prop[n * 4 + 2] * 0.25f, py1 = prop[n * 4 + 3] * 0.25f;
    const float bw = fmaxf(px1 - px0, 1.0f) * (1.0f / 7.0f);
    const float bh = fmaxf(py1 - py0, 1.0f) * (1.0f / 7.0f);

    __shared__ float sm[8 * 30 * 31];
    __shared__ int sx0[14], sx1[14], sy0[14], sy1[14];
    __shared__ float slx[14], sly[14];
    __shared__ int sb[4];

    if (tid < 14) {
        float g = ((float)tid + 0.5f) * 0.5f;
        float xc = fminf(fmaxf(px0 + g * bw, 0.0f), (float)(FW - 1));
        float yc = fminf(fmaxf(py0 + g * bh, 0.0f), (float)(FH - 1));
        int x0 = (int)floorf(xc), y0 = (int)floorf(yc);
        sx0[tid] = x0; sy0[tid] = y0;
        sx1[tid] = min(x0 + 1, FW - 1);
        sy1[tid] = min(y0 + 1, FH - 1);
        slx[tid] = xc - (float)x0;
        sly[tid] = yc - (float)y0;
    }
    __syncthreads();
    if (tid == 0) {
        sb[0] = sx0[0]; sb[1] = sy0[0];
        sb[2] = min(sx1[13] - sx0[0] + 1, 30);
        sb[3] = min(sy1[13] - sy0[0] + 1, 30);
    }
    __syncthreads();
    const int ixlo = sb[0], iylo = sb[1], wreg = sb[2], hreg = sb[3];
    const int wstr = wreg | 1;
    const int spx = hreg * wstr;

    {
        const int c = wid;
        const float* gsrc = feat + (((size_t)(b * CHAN + c0 + c) * FH) + iylo) * FW + ixlo + lane;
        float* sdst = &sm[c * spx] + lane;
        if (lane < wreg) {
            for (int y = 0; y < hreg; y++) sdst[y * wstr] = gsrc[y * FW];
        }
    }
    __syncthreads();

    for (int t = tid; t < 8 * 49; t += 256) {
        int c = t / 49, bin = t - c * 49;
        int by = bin / 7, bx = bin - by * 7;
        const float* base = &sm[c * spx];
        float acc = 0.0f;
#pragma unroll
        for (int sy = 0; sy < 2; sy++) {
            int s_y = by * 2 + sy;
            int ry0 = sy0[s_y] - iylo, ry1 = sy1[s_y] - iylo;
            float ly = sly[s_y];
#pragma unroll
            for (int sx = 0; sx < 2; sx++) {
                int s_x = bx * 2 + sx;
                int rx0 = sx0[s_x] - ixlo, rx1 = sx1[s_x] - ixlo;
                float lx = slx[s_x];
                acc += (1.0f - ly) * ((1.0f - lx) * base[ry0 * wstr + rx0] + lx * base[ry0 * wstr + rx1])
                     + ly * ((1.0f - lx) * base[ry1 * wstr + rx0] + lx * base[ry1 * wstr + rx1]);
            }
        }
        float v = acc * 0.25f;
        int idx = n * DFEAT + (c0 + c) * 49 + bin;
        __nv_bfloat16 hi = __float2bfloat16(v);
        g_ah[idx] = hi;
        g_al[idx] = __float2bfloat16(v - __bfloat162float(hi));
    }
}

#define ISSUE_TILE(kt_, buf_) do {                                                        \
    int kb = kbase + (kt_) * BK;                                                          \
    _Pragma("unroll")                                                                     \
    for (int sp = 0; sp < 2; sp++) {                                                      \
        const __nv_bfloat16* Ag = sp ? Al : Ah;                                           \
        _Pragma("unroll")                                                                 \
        for (int i = 0; i < 2; i++) {                                                     \
            int row = arow0 + 64 * i;                                                     \
            int gr = m0 + row;                                                            \
            int sz = (gr < NTOT) ? 16 : 0;                                                \
            int grc = (gr < NTOT) ? gr : (NTOT - 1);                                      \
            const void* g = (const void*)(Ag + (size_t)grc * K + kb + kc * 8);            \
            cp16(sbase + (uint32_t)(OFF_A(buf_, sp) + row * ASTR + kc * 8) * 2, g, sz);   \
        }                                                                                 \
        const __nv_bfloat16* Bg = sp ? Bl : Bh;                                           \
        _Pragma("unroll")                                                                 \
        for (int i = 0; i < 4; i++) {                                                     \
            int kr = bkr0 + 8 * i;                                                        \
            const void* g = (const void*)(Bg + (size_t)(kb + kr) * HID + n0 + nc * 8);    \
            cp16(sbase + (uint32_t)(OFF_B(buf_, sp) + kr * BSTR + nc * 8) * 2, g, 16);    \
        }                                                                                 \
    }                                                                                     \
    asm volatile("cp.async.commit_group;\n" ::);                                          \
} while (0)

// 3-stage pipeline, one __syncthreads per k-tile.
// grid: (m-tiles, n-tiles, S) — x fastest, so consecutive CTAs share the B tile (L2 reuse).
__global__ __launch_bounds__(256, 1)
void mma_gemm(const __nv_bfloat16* __restrict__ Ah, const __nv_bfloat16* __restrict__ Al,
              const __nv_bfloat16* __restrict__ Bh, const __nv_bfloat16* __restrict__ Bl,
              float* __restrict__ part, int K, int KPC) {
    extern __shared__ __align__(16) char smem_raw[];
    const uint32_t sbase = smem_u32(smem_raw);
    const int t = threadIdx.x, lane = t & 31, wid = t >> 5;
    const int wm = wid >> 2, wn = wid & 3;
    const int m0 = blockIdx.x * BM, n0 = blockIdx.y * BN;
    const int s = blockIdx.z;
    const int kbase = s * KPC;
    const int T = KPC / BK;
    const int arow0 = t >> 2, kc = t & 3, bkr0 = t >> 5, nc = t & 31;

    float acc[4][8][4];
#pragma unroll
    for (int i = 0; i < 4; i++)
#pragma unroll
        for (int j = 0; j < 8; j++)
#pragma unroll
            for (int q = 0; q < 4; q++) acc[i][j][q] = 0.0f;

    const int a_lrow = lane & 15, a_lk = (lane >> 4) * 8;
    const int b_lk = lane & 15, b_ln = (lane >> 4) * 8;

    ISSUE_TILE(0, 0);
    ISSUE_TILE(1, 1);

    int buf = 0;
    for (int kt = 0; kt < T; kt++) {
        asm volatile("cp.async.wait_group 1;\n" ::);
        __syncthreads();

        if (kt + 2 < T) {
            int nbuf = buf + 2; if (nbuf >= 3) nbuf -= 3;
            ISSUE_TILE(kt + 2, nbuf);
        } else {
            asm volatile("cp.async.commit_group;\n" ::);
        }

#pragma unroll
        for (int kk = 0; kk < 2; kk++) {
            uint32_t bhh[16], bll[16];
#pragma unroll
            for (int nfp = 0; nfp < 4; nfp++) {
                ldsm_x4_t(&bhh[nfp * 4], sbase +
                    (uint32_t)(OFF_B(buf, 0) + (kk * 16 + b_lk) * BSTR + wn * 64 + nfp * 16 + b_ln) * 2);
                ldsm_x4_t(&bll[nfp * 4], sbase +
                    (uint32_t)(OFF_B(buf, 1) + (kk * 16 + b_lk) * BSTR + wn * 64 + nfp * 16 + b_ln) * 2);
            }
#pragma unroll
            for (int mi = 0; mi < 4; mi++) {
                uint32_t ah[4], al[4];
                ldsm_x4(ah, sbase +
                    (uint32_t)(OFF_A(buf, 0) + (wm * 64 + mi * 16 + a_lrow) * ASTR + kk * 16 + a_lk) * 2);
                ldsm_x4(al, sbase +
                    (uint32_t)(OFF_A(buf, 1) + (wm * 64 + mi * 16 + a_lrow) * ASTR + kk * 16 + a_lk) * 2);
#pragma unroll
                for (int nf = 0; nf < 8; nf++) {
                    mma_bf16(acc[mi][nf], ah, bhh[2 * nf], bhh[2 * nf + 1]);
                    mma_bf16(acc[mi][nf], ah, bll[2 * nf], bll[2 * nf + 1]);
                    mma_bf16(acc[mi][nf], al, bhh[2 * nf], bhh[2 * nf + 1]);
                }
            }
        }
        if (++buf >= 3) buf = 0;
    }

    const size_t pbase = (size_t)s * NTOT * HID;
#pragma unroll
    for (int mi = 0; mi < 4; mi++) {
        int r0 = m0 + wm * 64 + mi * 16 + (lane >> 2);
        int r1 = r0 + 8;
#pragma unroll
        for (int nf = 0; nf < 8; nf++) {
            int col = n0 + wn * 64 + nf * 8 + (lane & 3) * 2;
            if (r0 < NTOT) {
                float2 v = {acc[mi][nf][0], acc[mi][nf][1]};
                *(float2*)&part[pbase + (size_t)r0 * HID + col] = v;
            }
            if (r1 < NTOT) {
                float2 v = {acc[mi][nf][2], acc[mi][nf][3]};
                *(float2*)&part[pbase + (size_t)r1 * HID + col] = v;
            }
        }
    }
}

__global__ void reduce_k(const float* __restrict__ part, const float* __restrict__ bias,
                         int S, int mode,
                         __nv_bfloat16* __restrict__ oh, __nv_bfloat16* __restrict__ ol,
                         float* __restrict__ of) {
    int idx = blockIdx.x * blockDim.x + threadIdx.x;
    if (idx >= NTOT * HID) return;
    float v = 0.0f;
    for (int s = 0; s < S; s++) v += part[(size_t)s * NTOT * HID + idx];
    v = fmaxf(v + bias[idx & 1023], 0.0f);
    if (mode == 0) {
        __nv_bfloat16 hi = __float2bfloat16(v);
        oh[idx] = hi;
        ol[idx] = __float2bfloat16(v - __bfloat162float(hi));
    } else of[idx] = v;
}

__global__ void heads_kernel(const float* __restrict__ h,
                             const float* __restrict__ bc,
                             const float* __restrict__ bb) {
    const int n = blockIdx.x, tid = threadIdx.x, lane = tid & 31, wid = tid >> 5;
    __shared__ float row[HID];
    for (int t = tid; t < HID; t += 256) row[t] = h[n * HID + t];
    __syncthreads();
    for (int j = 0; j < 5; j++) {
        int o = wid + 8 * j;
        if (o >= 35) break;
        const float* w = &g_wt[o * HID];
        float v = 0.0f;
        for (int k = lane; k < HID; k += 32) v += row[k] * w[k];
#pragma unroll
        for (int off = 16; off > 0; off >>= 1) v += __shfl_down_sync(0xffffffffu, v, off);
        if (lane == 0) {
            if (o < 7) g_logits[n * 7 + o] = v + bc[o];
            else       g_deltas[n * 28 + (o - 7)] = v + bb[o - 7];
        }
    }
}

__global__ void decode_kernel(const float* __restrict__ prop) {
    int m = blockIdx.x * blockDim.x + threadIdx.x;
    if (m >= NTOT * K1CL) return;
    int n = m / K1CL, k = 1 + (m - n * K1CL);
    int b = n / PROPS, p = n - b * PROPS;
    float l[7];
#pragma unroll
    for (int i = 0; i < 7; i++) l[i] = g_logits[n * 7 + i];
    float mx = l[0];
#pragma unroll
    for (int i = 1; i < 7; i++) mx = fmaxf(mx, l[i]);
    float s = 0.0f;
#pragma unroll
    for (int i = 0; i < 7; i++) s += expf(l[i] - mx);
    float pr = expf(l[k] - mx) / s;
    float p0 = prop[n * 4 + 0], p1 = prop[n * 4 + 1];
    float p2 = prop[n * 4 + 2], p3 = prop[n * 4 + 3];
    float w = p2 - p0, h = p3 - p1;
    float cx = p0 + 0.5f * w, cy = p1 + 0.5f * h;
    const float* d = &g_deltas[n * 28 + k * 4];
    float dx = d[0] / 10.0f, dy = d[1] / 10.0f;
    float dw = fminf(d[2] / 5.0f, BBOX_CLIP), dh = fminf(d[3] / 5.0f, BBOX_CLIP);
    float pcx = dx * w + cx, pcy = dy * h + cy;
    float pw = expf(dw) * w, ph = expf(dh) * h;
    float x1 = fminf(fmaxf(pcx - 0.5f * pw, 0.0f), 800.0f);
    float y1 = fminf(fmaxf(pcy - 0.5f * ph, 0.0f), 800.0f);
    float x2 = fminf(fmaxf(pcx + 0.5f * pw, 0.0f), 800.0f);
    float y2 = fminf(fmaxf(pcy + 0.5f * ph, 0.0f), 800.0f);
    int ci = b * CANDS + p * K1CL + (k - 1);
    g_cbox[ci * 4 + 0] = x1; g_cbox[ci * 4 + 1] = y1;
    g_cbox[ci * 4 + 2] = x2; g_cbox[ci * 4 + 3] = y2;
    float off = (float)k * 802.0f;
    float ox1 = x1 + off, oy1 = y1 + off, ox2 = x2 + off, oy2 = y2 + off;
    g_cob[ci * 4 + 0] = ox1; g_cob[ci * 4 + 1] = oy1;
    g_cob[ci * 4 + 2] = ox2; g_cob[ci * 4 + 3] = oy2;
    g_carea[ci] = (ox2 - ox1) * (oy2 - oy1);
    g_cscore[ci] = pr;
    g_clab[ci] = k;
    bool valid = (pr > 0.05f) && ((x2 - x1) >= 0.01f) && ((y2 - y1) >= 0.01f);
    g_csw[ci] = valid ? pr : NEGV;
}

__global__ void nms_kernel(float* __restrict__ out) {
    const int b = blockIdx.x, tid = threadIdx.x;
    __shared__ float sob[CANDS * 4], sarea[CANDS], ssw[CANDS];
    __shared__ float rv[32];
    __shared__ int ri[32];
    __shared__ int s_j;
    __shared__ float s_s;
    __shared__ int pj[DETS];
    __shared__ float ps[DETS];
    for (int t = tid; t < CANDS; t += 1024) {
        int g = b * CANDS + t;
        sob[t * 4 + 0] = g_cob[g * 4 + 0];
        sob[t * 4 + 1] = g_cob[g * 4 + 1];
        sob[t * 4 + 2] = g_cob[g * 4 + 2];
        sob[t * 4 + 3] = g_cob[g * 4 + 3];
        sarea[t] = g_carea[g];
        ssw[t] = g_csw[g];
    }
    __syncthreads();
    const int lane = tid & 31, warp = tid >> 5;
    for (int it = 0; it < DETS; it++) {
        float bv = -FLT_MAX;
        int bi = CANDS;
        {
            float v = ssw[tid];
            if (v > bv || (v == bv && tid < bi)) { bv = v; bi = tid; }
            int i2 = tid + 1024;
            if (i2 < CANDS) {
                float v2 = ssw[i2];
                if (v2 > bv || (v2 == bv && i2 < bi)) { bv = v2; bi = i2; }
            }
        }
#pragma unroll
        for (int off = 16; off > 0; off >>= 1) {
            float ov = __shfl_down_sync(0xffffffffu, bv, off);
            int   oi = __shfl_down_sync(0xffffffffu, bi, off);
            if (ov > bv || (ov == bv && oi < bi)) { bv = ov; bi = oi; }
        }
        if (lane == 0) { rv[warp] = bv; ri[warp] = bi; }
        __syncthreads();
        if (warp == 0) {
            float v = rv[lane];
            int i = ri[lane];
#pragma unroll
            for (int off = 16; off > 0; off >>= 1) {
                float ov = __shfl_down_sync(0xffffffffu, v, off);
                int   oi = __shfl_down_sync(0xffffffffu, i, off);
                if (ov > v || (ov == v && oi < i)) { v = ov; i = oi; }
            }
            if (lane == 0) { s_j = i; s_s = v; }
        }
        __syncthreads();
        int j = s_j;
        if (tid == 0) { pj[it] = j; ps[it] = s_s; }
        float jx1 = sob[j * 4 + 0], jy1 = sob[j * 4 + 1];
        float jx2 = sob[j * 4 + 2], jy2 = sob[j * 4 + 3];
        float ja = sarea[j];
        for (int i = tid; i < CANDS; i += 1024) {
            float xx1 = fmaxf(jx1, sob[i * 4 + 0]);
            float yy1 = fmaxf(jy1, sob[i * 4 + 1]);
            float xx2 = fminf(jx2, sob[i * 4 + 2]);
            float yy2 = fminf(jy2, sob[i * 4 + 3]);
            float inter = fmaxf(xx2 - xx1, 0.0f) * fmaxf(yy2 - yy1, 0.0f);
            float iou = inter / (ja + sarea[i] - inter + 1e-9f);
            if (iou > 0.5f || i == j) ssw[i] = NEGV;
        }
        __syncthreads();
    }
    if (tid < DETS) {
        int j = pj[tid];
        bool kv = ps[tid] > -5e29f;
        float bx0 = 0, bx1 = 0, bx2 = 0, bx3 = 0, sc = 0, lb = 0;
        if (kv) {
            int g = b * CANDS + j;
            bx0 = g_cbox[g * 4 + 0]; bx1 = g_cbox[g * 4 + 1];
            bx2 = g_cbox[g * 4 + 2]; bx3 = g_cbox[g * 4 + 3];
            sc = g_cscore[g];
            lb = (float)g_clab[g];
        }
        int base = (b * DETS + tid) * 4;
        out[base + 0] = bx0; out[base + 1] = bx1;
        out[base + 2] = bx2; out[base + 3] = bx3;
        out[BATCH * DETS * 4 + b * DETS + tid] = sc;
        out[BATCH * DETS * 4 + BATCH * DETS + b * DETS + tid] = lb;
    }
}

extern "C" void kernel_launch(void* const* d_in, const int* in_sizes, int n_in,
                              void* d_out, int out_size) {
    const float* feat = (const float*)d_in[0];
    const float* prop = (const float*)d_in[1];
    const float* w1 = (const float*)d_in[2];
    const float* b1 = (const float*)d_in[3];
    const float* w2 = (const float*)d_in[4];
    const float* b2 = (const float*)d_in[5];
    const float* wc = (const float*)d_in[6];
    const float* bc = (const float*)d_in[7];
    const float* wb = (const float*)d_in[8];
    const float* bb = (const float*)d_in[9];
    float* out = (float*)d_out;

    void *p_ah, *p_al, *p_w1h, *p_w1l, *p_w2h, *p_w2l, *p_h1h, *p_h1l, *p_h2, *p_part;
    cudaGetSymbolAddress(&p_ah, g_ah);   cudaGetSymbolAddress(&p_al, g_al);
    cudaGetSymbolAddress(&p_w1h, g_w1h); cudaGetSymbolAddress(&p_w1l, g_w1l);
    cudaGetSymbolAddress(&p_w2h, g_w2h); cudaGetSymbolAddress(&p_w2l, g_w2l);
    cudaGetSymbolAddress(&p_h1h, g_h1h); cudaGetSymbolAddress(&p_h1l, g_h1l);
    cudaGetSymbolAddress(&p_h2, g_h2);   cudaGetSymbolAddress(&p_part, g_part);

    static int smem_set = 0;
    if (!smem_set) {
        cudaFuncSetAttribute(mma_gemm, cudaFuncAttributeMaxDynamicSharedMemorySize, SMEM_BYTES);
        smem_set = 1;
    }

    const int n4w1 = DFEAT * HID / 4, n4w2 = HID * HID / 4;

    roi_align_kernel<<<dim3(NTOT, 64), 256>>>(feat, prop);
    split_kernel<<<(n4w1 + 255) / 256, 256>>>((const float4*)w1,
        (__nv_bfloat162*)p_w1h, (__nv_bfloat162*)p_w1l, n4w1);
    wt_build<<<140, 256>>>(wc, wb);

    mma_gemm<<<dim3((NTOT + BM - 1) / BM, HID / BN, 14), 256, SMEM_BYTES>>>(
        (const __nv_bfloat16*)p_ah, (const __nv_bfloat16*)p_al,
        (const __nv_bfloat16*)p_w1h, (const __nv_bfloat16*)p_w1l,
        (float*)p_part, DFEAT, 1792);

    split_kernel<<<(n4w2 + 255) / 256, 256>>>((const float4*)w2,
        (__nv_bfloat162*)p_w2h, (__nv_bfloat162*)p_w2l, n4w2);
    reduce_k<<<(NTOT * HID + 255) / 256, 256>>>((const float*)p_part, b1, 14, 0,
        (__nv_bfloat16*)p_h1h, (__nv_bfloat16*)p_h1l, nullptr);

    mma_gemm<<<dim3((NTOT + BM - 1) / BM, HID / BN, 8), 256, SMEM_BYTES>>>(
        (const __nv_bfloat16*)p_h1h, (const __nv_bfloat16*)p_h1l,
        (const __nv_bfloat16*)p_w2h, (const __nv_bfloat16*)p_w2l,
        (float*)p_part, HID, 128);
    reduce_k<<<(NTOT * HID + 255) / 256, 256>>>((const float*)p_part, b2, 8, 1,
        nullptr, nullptr, (float*)p_h2);

    heads_kernel<<<NTOT, 256>>>((const float*)p_h2, bc, bb);
    decode_kernel<<<(NTOT * K1CL + 255) / 256, 256>>>(prop);
    nms_kernel<<<BATCH, 1024>>>(out);
}